// round 15
// baseline (speedup 1.0000x reference)
#include <cuda_runtime.h>
#include <cuda_bf16.h>
#include <cuda_fp16.h>
#include <math.h>
#include <stdint.h>

#define B 8
#define L 2048
#define D 1024

__device__ float         g_scores[(size_t)B * L * L];
__device__ __half        g_probs[(size_t)B * L * L];
__device__ __nv_bfloat16 g_qh[(size_t)B * L * D];
__device__ __nv_bfloat16 g_ql[(size_t)B * L * D];
__device__ __nv_bfloat16 g_kh[(size_t)B * L * D];
__device__ __nv_bfloat16 g_kl[(size_t)B * L * D];
__device__ __half        g_vt[(size_t)B * L * D];   // gathered V^T: [b][d][jj]
__device__ int           g_idx[B * L];
__device__ int           g_nv[B];

#define GEMM_GRID 444   // 3 CTAs/SM * 148 SMs

// ---------------------------------------------------------------------------
__device__ __forceinline__ uint32_t smem_u32(const void* p) {
    uint32_t a;
    asm("{ .reg .u64 t; cvta.to.shared.u64 t, %1; cvt.u32.u64 %0, t; }" : "=r"(a) : "l"(p));
    return a;
}
__device__ __forceinline__ void cp16(uint32_t dst, const void* src) {
    asm volatile("cp.async.cg.shared.global [%0], [%1], 16;" :: "r"(dst), "l"(src) : "memory");
}
#define CP_COMMIT() asm volatile("cp.async.commit_group;" ::: "memory")
#define CP_WAIT(n)  asm volatile("cp.async.wait_group %0;" :: "n"(n) : "memory")

__device__ __forceinline__ void mma_bf16(float c[4], uint32_t a0, uint32_t a1,
                                         uint32_t a2, uint32_t a3,
                                         uint32_t b0, uint32_t b1) {
    asm volatile(
        "mma.sync.aligned.m16n8k16.row.col.f32.bf16.bf16.f32 "
        "{%0,%1,%2,%3}, {%4,%5,%6,%7}, {%8,%9}, {%0,%1,%2,%3};"
        : "+f"(c[0]), "+f"(c[1]), "+f"(c[2]), "+f"(c[3])
        : "r"(a0), "r"(a1), "r"(a2), "r"(a3), "r"(b0), "r"(b1));
}
__device__ __forceinline__ void mma_f16(float c[4], uint32_t a0, uint32_t a1,
                                        uint32_t a2, uint32_t a3,
                                        uint32_t b0, uint32_t b1) {
    asm volatile(
        "mma.sync.aligned.m16n8k16.row.col.f32.f16.f16.f32 "
        "{%0,%1,%2,%3}, {%4,%5,%6,%7}, {%8,%9}, {%0,%1,%2,%3};"
        : "+f"(c[0]), "+f"(c[1]), "+f"(c[2]), "+f"(c[3])
        : "r"(a0), "r"(a1), "r"(a2), "r"(a3), "r"(b0), "r"(b1));
}

// ---------------------------------------------------------------------------
// Kernel 0a: per-batch compaction of valid indices
// ---------------------------------------------------------------------------
__global__ __launch_bounds__(256) void compact_kernel(const int* __restrict__ mask)
{
    const int b = blockIdx.x;
    const int tid = threadIdx.x, lane = tid & 31, wid = tid >> 5;
    const int* mb = mask + b * L;
    __shared__ int wsum[8];

    int m[8];
    int4 a = *(const int4*)(mb + tid * 8);
    int4 c = *(const int4*)(mb + tid * 8 + 4);
    m[0]=a.x; m[1]=a.y; m[2]=a.z; m[3]=a.w;
    m[4]=c.x; m[5]=c.y; m[6]=c.z; m[7]=c.w;

    int tot = 0;
    #pragma unroll
    for (int e = 0; e < 8; e++) tot += m[e];

    int inc = tot;
    #pragma unroll
    for (int o = 1; o < 32; o <<= 1) {
        int v = __shfl_up_sync(0xffffffffu, inc, o);
        if (lane >= o) inc += v;
    }
    if (lane == 31) wsum[wid] = inc;
    __syncthreads();
    int woff = 0;
    #pragma unroll
    for (int w = 0; w < 8; w++) if (w < wid) woff += wsum[w];

    int pos = woff + inc - tot;
    #pragma unroll
    for (int e = 0; e < 8; e++)
        if (m[e]) g_idx[b * L + pos++] = tid * 8 + e;

    if (tid == 255) g_nv[b] = woff + inc;
}

// ---------------------------------------------------------------------------
// Kernel 0b: zero-fill output rows with m_i == 0 (runs last)
// ---------------------------------------------------------------------------
__global__ __launch_bounds__(256) void zerofill_kernel(
    const int* __restrict__ mask, float* __restrict__ out)
{
    const int row = blockIdx.x;
    const int b = row >> 11, i = row & (L - 1);
    if (mask[b * L + i]) return;
    float4 z = make_float4(0.f, 0.f, 0.f, 0.f);
    *(float4*)(out + ((size_t)b * L + i) * D + threadIdx.x * 4) = z;
}

// ---------------------------------------------------------------------------
// Prep 1: gather q,k valid rows -> bf16 hi/lo, k-pair-interleaved layout.
// ---------------------------------------------------------------------------
__global__ __launch_bounds__(256) void prep_qk_kernel(
    const float* __restrict__ q, const float* __restrict__ k)
{
    const float* src = blockIdx.y ? k : q;
    __nv_bfloat16* dh = blockIdx.y ? g_kh : g_qh;
    __nv_bfloat16* dl = blockIdx.y ? g_kl : g_ql;
    size_t gi = (size_t)blockIdx.x * 256 + threadIdx.x;
    const int row = (int)(gi >> 6);
    const int b = row >> 11, ii = row & (L - 1);
    if (ii >= g_nv[b]) return;
    const int gidx = g_idx[b * L + ii];
    const float* s = src + ((size_t)b * L + gidx) * D + (gi & 63) * 16;

    uint32_t h[8], l[8];
    #pragma unroll
    for (int qd = 0; qd < 4; ++qd) {
        float4 x = *(const float4*)(s + 4 * qd);
        __nv_bfloat162 h0 = __floats2bfloat162_rn(x.x, x.y);
        __nv_bfloat162 h1 = __floats2bfloat162_rn(x.z, x.w);
        float2 b0 = __bfloat1622float2(h0), b1 = __bfloat1622float2(h1);
        __nv_bfloat162 l0 = __floats2bfloat162_rn(x.x - b0.x, x.y - b0.y);
        __nv_bfloat162 l1 = __floats2bfloat162_rn(x.z - b1.x, x.w - b1.y);
        h[2*qd] = *(uint32_t*)&h0; h[2*qd+1] = *(uint32_t*)&h1;
        l[2*qd] = *(uint32_t*)&l0; l[2*qd+1] = *(uint32_t*)&l1;
    }
    *(uint4*)(dh + gi * 16)     = make_uint4(h[0], h[4], h[1], h[5]);
    *(uint4*)(dh + gi * 16 + 8) = make_uint4(h[2], h[6], h[3], h[7]);
    *(uint4*)(dl + gi * 16)     = make_uint4(l[0], l[4], l[1], l[5]);
    *(uint4*)(dl + gi * 16 + 8) = make_uint4(l[2], l[6], l[3], l[7]);
}

// ---------------------------------------------------------------------------
// Prep 2: gather V valid rows, f32 [b][j][d] -> fp16 transposed [b][d][jj].
// ---------------------------------------------------------------------------
__global__ __launch_bounds__(256) void prep_v_kernel(const float* __restrict__ v)
{
    __shared__ __half t[32][72];
    const int b = blockIdx.z, d0 = blockIdx.y * 32, j0 = blockIdx.x * 64;
    const int nv = g_nv[b];
    const int tid = threadIdx.x;
    const int dd = tid & 31, jw = tid >> 5;
    #pragma unroll
    for (int it = 0; it < 8; ++it) {
        int jj = jw + it * 8;
        int jg = j0 + jj;
        float x = 0.0f;
        if (jg < nv) x = v[((size_t)b * L + g_idx[b * L + jg]) * D + d0 + dd];
        t[dd][jj] = __float2half_rn(x);
    }
    __syncthreads();
    const int row = tid >> 3, c8 = (tid & 7) * 8;
    uint32_t u[4];
    #pragma unroll
    for (int e = 0; e < 4; ++e) {
        __half2 hp; hp.x = t[row][c8 + 2*e]; hp.y = t[row][c8 + 2*e + 1];
        u[e] = *(uint32_t*)&hp;
    }
    *(uint4*)(g_vt + ((size_t)b * D + d0 + row) * L + j0 + c8) =
        make_uint4(u[0], u[1], u[2], u[3]);
}

// ---------------------------------------------------------------------------
// Kernel 1: compacted S = Qc Kc^T, bf16 3-term split.
// 128 thr, 4 warps 2x2, warp tile 64x64. BK=16, RS=32 (tight, bank-perfect),
// 4 stages (16KB each), 3 CTAs/SM, wait_group(2). Low-reg 3-pass compute.
// ---------------------------------------------------------------------------
#define QK_RS    32
#define QK_TILE  (128 * QK_RS)       // 4096
#define QK_STAGE (4 * QK_TILE)       // 16384
#define QK_NC    (D / 16)            // 64 stages

__global__ __launch_bounds__(128, 3) void qk_kernel()
{
    extern __shared__ char sm[];
    const uint32_t smbase = smem_u32(sm);
    const int tid = threadIdx.x, lane = tid & 31, wid = tid >> 5;
    const int g = lane >> 2, t = lane & 3;
    const int rm = (wid >> 1) * 64, rn = (wid & 1) * 64;

    int ntl[8], pre[9];
    pre[0] = 0;
    #pragma unroll
    for (int bb = 0; bb < 8; ++bb) {
        ntl[bb] = (g_nv[bb] + 127) >> 7;
        pre[bb + 1] = pre[bb] + ntl[bb] * ntl[bb];
    }
    const int total = pre[8];

    for (int tile = blockIdx.x; tile < total; tile += GEMM_GRID) {
        int b = 0;
        #pragma unroll
        for (int bb = 0; bb < 8; ++bb) if (tile >= pre[bb + 1]) b = bb + 1;
        const int loc = tile - pre[b];
        const int nt = ntl[b];
        const int ty = loc / nt, tx = loc - ty * nt;
        const int ti = ty * 128, tj = tx * 128;

        const __nv_bfloat16* qh = g_qh + ((size_t)b * L + ti) * D;
        const __nv_bfloat16* ql = g_ql + ((size_t)b * L + ti) * D;
        const __nv_bfloat16* kh = g_kh + ((size_t)b * L + tj) * D;
        const __nv_bfloat16* kl = g_kl + ((size_t)b * L + tj) * D;

        float acc[4][8][4];
        #pragma unroll
        for (int a = 0; a < 4; a++)
            #pragma unroll
            for (int bb = 0; bb < 8; bb++)
                #pragma unroll
                for (int cc = 0; cc < 4; cc++) acc[a][bb][cc] = 0.0f;

        // loader: 8 cp16/thread; thread = row, sg = half-row (16B)
        #define QK_LOAD(c, st) do { \
            uint32_t sb = smbase + (st) * QK_STAGE + (uint32_t)tid * QK_RS; \
            const size_t go = (size_t)tid * D + (size_t)(c) * 16; \
            _Pragma("unroll") \
            for (int e = 0; e < 8; ++e) { \
                const int tl = e >> 1, sg = e & 1; \
                const __nv_bfloat16* gs = (tl == 0) ? qh : (tl == 1) ? ql \
                                        : (tl == 2) ? kh : kl; \
                cp16(sb + tl * QK_TILE + sg * 16, gs + go + sg * 8); \
            } } while (0)

        // single k16 step; low-reg 3 passes (af reused; B reloaded pass 3)
        #define QK_COMPUTE(buf) do { \
            const char* Qh_ = sm + (buf) * QK_STAGE; \
            const char* Ql_ = Qh_ + QK_TILE; \
            const char* Kh_ = Qh_ + 2 * QK_TILE; \
            const char* Kl_ = Qh_ + 3 * QK_TILE; \
            const uint32_t so = (uint32_t)(t * 8); \
            uint2 af[4][2]; \
            _Pragma("unroll") \
            for (int mt = 0; mt < 4; ++mt) { \
                uint32_t r0 = (uint32_t)(rm + mt * 16 + g) * QK_RS + so; \
                af[mt][0] = *(const uint2*)(Qh_ + r0); \
                af[mt][1] = *(const uint2*)(Qh_ + r0 + 8 * QK_RS); \
            } \
            _Pragma("unroll") \
            for (int nt2 = 0; nt2 < 8; ++nt2) { \
                uint32_t rb = (uint32_t)(rn + nt2 * 8 + g) * QK_RS + so; \
                uint2 bf = *(const uint2*)(Kh_ + rb); \
                _Pragma("unroll") \
                for (int mt = 0; mt < 4; ++mt) \
                    mma_bf16(acc[mt][nt2], af[mt][0].x, af[mt][1].x, af[mt][0].y, af[mt][1].y, bf.x, bf.y); \
            } \
            _Pragma("unroll") \
            for (int nt2 = 0; nt2 < 8; ++nt2) { \
                uint32_t rb = (uint32_t)(rn + nt2 * 8 + g) * QK_RS + so; \
                uint2 bf = *(const uint2*)(Kl_ + rb); \
                _Pragma("unroll") \
                for (int mt = 0; mt < 4; ++mt) \
                    mma_bf16(acc[mt][nt2], af[mt][0].x, af[mt][1].x, af[mt][0].y, af[mt][1].y, bf.x, bf.y); \
            } \
            _Pragma("unroll") \
            for (int mt = 0; mt < 4; ++mt) { \
                uint32_t r0 = (uint32_t)(rm + mt * 16 + g) * QK_RS + so; \
                af[mt][0] = *(const uint2*)(Ql_ + r0); \
                af[mt][1] = *(const uint2*)(Ql_ + r0 + 8 * QK_RS); \
            } \
            _Pragma("unroll") \
            for (int nt2 = 0; nt2 < 8; ++nt2) { \
                uint32_t rb = (uint32_t)(rn + nt2 * 8 + g) * QK_RS + so; \
                uint2 bf = *(const uint2*)(Kh_ + rb); \
                _Pragma("unroll") \
                for (int mt = 0; mt < 4; ++mt) \
                    mma_bf16(acc[mt][nt2], af[mt][0].x, af[mt][1].x, af[mt][0].y, af[mt][1].y, bf.x, bf.y); \
            } } while (0)

        QK_LOAD(0, 0); CP_COMMIT();
        QK_LOAD(1, 1); CP_COMMIT();
        QK_LOAD(2, 2); CP_COMMIT();
        for (int c = 0; c < QK_NC; ++c) {
            CP_WAIT(2);
            __syncthreads();
            if (c + 3 < QK_NC) { QK_LOAD(c + 3, (c + 3) & 3); }
            CP_COMMIT();
            QK_COMPUTE(c & 3);
        }

        #pragma unroll
        for (int mt = 0; mt < 4; ++mt) {
            int r0 = rm + mt * 16 + g;
            float* row0 = g_scores + ((size_t)b * L + ti + r0) * L + tj;
            float* row1 = row0 + (size_t)8 * L;
            #pragma unroll
            for (int nt2 = 0; nt2 < 8; ++nt2) {
                int c0 = rn + nt2 * 8 + 2 * t;
                *(float2*)(row0 + c0) = make_float2(acc[mt][nt2][0], acc[mt][nt2][1]);
                *(float2*)(row1 + c0) = make_float2(acc[mt][nt2][2], acc[mt][nt2][3]);
            }
        }
        __syncthreads();
    }
}

// ---------------------------------------------------------------------------
// Kernel 2: softmax over compacted row (length nv).
// ---------------------------------------------------------------------------
__global__ __launch_bounds__(256) void rowstats_kernel()
{
    const int row = blockIdx.x;
    const int b = row >> 11;
    const int ii = row & (L - 1);
    const int nv = g_nv[b];
    if (ii >= nv) return;
    const float* s = g_scores + (size_t)row * L;
    const int tid = threadIdx.x;
    const int base = tid * 8;

    float vv[8];
    if (base + 8 <= nv) {
        float4 v0 = *(const float4*)(s + base);
        float4 v1 = *(const float4*)(s + base + 4);
        vv[0]=v0.x; vv[1]=v0.y; vv[2]=v0.z; vv[3]=v0.w;
        vv[4]=v1.x; vv[5]=v1.y; vv[6]=v1.z; vv[7]=v1.w;
    } else {
        #pragma unroll
        for (int e = 0; e < 8; e++)
            vv[e] = (base + e < nv) ? s[base + e] : -INFINITY;
    }

    __shared__ float sredA[8], sredB[8];
    const unsigned full = 0xffffffffu;

    float lmax = vv[0];
    #pragma unroll
    for (int e = 1; e < 8; e++) lmax = fmaxf(lmax, vv[e]);
    #pragma unroll
    for (int o = 16; o > 0; o >>= 1) lmax = fmaxf(lmax, __shfl_xor_sync(full, lmax, o));
    if ((tid & 31) == 0) sredA[tid >> 5] = lmax;
    __syncthreads();
    float bmax = sredA[0];
    #pragma unroll
    for (int w = 1; w < 8; w++) bmax = fmaxf(bmax, sredA[w]);
    if (nv < L) bmax = fmaxf(bmax, 0.0f);

    float p[8];
    float lsum = 0.0f;
    #pragma unroll
    for (int e = 0; e < 8; e++) { p[e] = __expf(vv[e] - bmax); lsum += p[e]; }
    #pragma unroll
    for (int o = 16; o > 0; o >>= 1) lsum += __shfl_xor_sync(full, lsum, o);
    if ((tid & 31) == 0) sredB[tid >> 5] = lsum;
    __syncthreads();
    float bsum = 0.0f;
    #pragma unroll
    for (int w = 0; w < 8; w++) bsum += sredB[w];

    const float denom = bsum + ((bsum == 0.0f) ? 1.0f : 0.0f) + 1e-20f;
    const float scale = 1.0f / denom;

    const int ncpad = ((nv + 63) >> 6) << 6;
    if (base < ncpad) {
        uint32_t u[4];
        #pragma unroll
        for (int e = 0; e < 4; ++e) {
            __half2 hp = __floats2half2_rn(p[2*e] * scale, p[2*e+1] * scale);
            u[e] = *(uint32_t*)&hp;
        }
        *(uint4*)(g_probs + (size_t)row * L + base) = make_uint4(u[0], u[1], u[2], u[3]);
    }
}

// ---------------------------------------------------------------------------
// Kernel 3: Oc = Pc Vc (fp16 mma). 128 thr, 4 warps 2x2, warp tile 64x64,
// BK=64, 2 stages, 3 CTAs/SM, dense tile scheduling. B-frags reloaded per nt2.
// ---------------------------------------------------------------------------
#define PV_RS    144
#define PV_TILE  (128 * PV_RS)       // 18432
#define PV_STAGE (2 * PV_TILE)       // 36864

__global__ __launch_bounds__(128, 3) void pv_kernel(float* __restrict__ out)
{
    extern __shared__ char sm[];
    const uint32_t smbase = smem_u32(sm);
    const int tid = threadIdx.x, lane = tid & 31, wid = tid >> 5;
    const int g = lane >> 2, t = lane & 3;
    const int rm = (wid >> 1) * 64, rn = (wid & 1) * 64;

    int ntl[8], pre[9];
    pre[0] = 0;
    #pragma unroll
    for (int bb = 0; bb < 8; ++bb) {
        ntl[bb] = (g_nv[bb] + 127) >> 7;
        pre[bb + 1] = pre[bb] + ntl[bb] * 8;
    }
    const int total = pre[8];

    for (int tile = blockIdx.x; tile < total; tile += GEMM_GRID) {
        int b = 0;
        #pragma unroll
        for (int bb = 0; bb < 8; ++bb) if (tile >= pre[bb + 1]) b = bb + 1;
        const int loc = tile - pre[b];
        const int ty = loc >> 3, txd = loc & 7;
        const int ti = ty * 128, td = txd * 128;
        const int nv = g_nv[b];
        const int NC = (nv + 63) >> 6;

        const __half* pb  = g_probs + ((size_t)b * L + ti) * L;
        const __half* vtb = g_vt + ((size_t)b * D + td) * L;

        float acc[4][8][4];
        #pragma unroll
        for (int a = 0; a < 4; a++)
            #pragma unroll
            for (int bb = 0; bb < 8; bb++)
                #pragma unroll
                for (int cc = 0; cc < 4; cc++) acc[a][bb][cc] = 0.0f;

        // loader: 2048 granules/stage, 16/thread
        #define PV_LOAD(c, st) do { \
            uint32_t sb = smbase + (st) * PV_STAGE; \
            _Pragma("unroll") \
            for (int e = 0; e < 16; ++e) { \
                const int tl = e >> 3; \
                int rc = (e & 7) * 128 + tid; \
                int r = rc >> 3, cg = rc & 7; \
                uint32_t doff = (uint32_t)tl * PV_TILE + (uint32_t)r * PV_RS + cg * 16; \
                size_t goff = (size_t)r * L + (size_t)(c) * 64 + cg * 8; \
                cp16(sb + doff, (tl ? vtb : pb) + goff); \
            } } while (0)

        #define PV_COMPUTE(buf) do { \
            const char* Pt = sm + (buf) * PV_STAGE; \
            const char* Vt = Pt + PV_TILE; \
            _Pragma("unroll") \
            for (int s = 0; s < 4; ++s) { \
                const uint32_t so = (uint32_t)(32 * s + 4 * t); \
                uint32_t a0[4], a1[4], a2[4], a3[4]; \
                _Pragma("unroll") \
                for (int mt = 0; mt < 4; ++mt) { \
                    uint32_t r0 = (uint32_t)(rm + mt * 16 + g) * PV_RS + so; \
                    a0[mt] = *(const uint32_t*)(Pt + r0); \
                    a2[mt] = *(const uint32_t*)(Pt + r0 + 16); \
                    a1[mt] = *(const uint32_t*)(Pt + r0 + 8 * PV_RS); \
                    a3[mt] = *(const uint32_t*)(Pt + r0 + 8 * PV_RS + 16); \
                } \
                _Pragma("unroll") \
                for (int nt2 = 0; nt2 < 8; ++nt2) { \
                    uint32_t rb = (uint32_t)(rn + nt2 * 8 + g) * PV_RS + so; \
                    uint32_t b0 = *(const uint32_t*)(Vt + rb); \
                    uint32_t b1 = *(const uint32_t*)(Vt + rb + 16); \
                    _Pragma("unroll") \
                    for (int mt = 0; mt < 4; ++mt) \
                        mma_f16(acc[mt][nt2], a0[mt], a1[mt], a2[mt], a3[mt], b0, b1); \
                } \
            } } while (0)

        PV_LOAD(0, 0); CP_COMMIT();
        for (int c = 0; c < NC; ++c) {
            CP_WAIT(0);
            __syncthreads();
            if (c + 1 < NC) { PV_LOAD(c + 1, (c + 1) & 1); CP_COMMIT(); }
            PV_COMPUTE(c & 1);
        }

        const int* idxb = g_idx + b * L;
        #pragma unroll
        for (int mt = 0; mt < 4; ++mt) {
            int r0 = rm + mt * 16 + g;
            int i0 = ti + r0, i1 = i0 + 8;
            #pragma unroll
            for (int half = 0; half < 2; ++half) {
                int irow = half ? i1 : i0;
                if (irow < nv) {
                    float* orow = out + ((size_t)b * L + idxb[irow]) * D + td;
                    #pragma unroll
                    for (int nt2 = 0; nt2 < 8; ++nt2) {
                        int c0 = rn + nt2 * 8 + 2 * t;
                        *(float2*)(orow + c0) = half
                            ? make_float2(acc[mt][nt2][2], acc[mt][nt2][3])
                            : make_float2(acc[mt][nt2][0], acc[mt][nt2][1]);
                    }
                }
            }
        }
        __syncthreads();
    }
}

// ---------------------------------------------------------------------------
extern "C" void kernel_launch(void* const* d_in, const int* in_sizes, int n_in,
                              void* d_out, int out_size)
{
    const float* q    = (const float*)d_in[0];
    const float* k    = (const float*)d_in[1];
    const float* v    = (const float*)d_in[2];
    const int*   mask = (const int*)d_in[3];
    float*       out  = (float*)d_out;

    cudaFuncSetAttribute(qk_kernel, cudaFuncAttributeMaxDynamicSharedMemorySize, 4 * QK_STAGE);
    cudaFuncSetAttribute(pv_kernel, cudaFuncAttributeMaxDynamicSharedMemorySize, 2 * PV_STAGE);

    compact_kernel<<<B, 256>>>(mask);
    prep_qk_kernel<<<dim3((B * L * D / 16) / 256, 2, 1), 256>>>(q, k);
    prep_v_kernel<<<dim3(L / 64, D / 32, B), 256>>>(v);

    qk_kernel<<<GEMM_GRID, 128, 4 * QK_STAGE>>>();   // slot #4 -> ncu sample

    rowstats_kernel<<<B * L, 256>>>();

    pv_kernel<<<GEMM_GRID, 128, 2 * PV_STAGE>>>(out);

    zerofill_kernel<<<B * L, 256>>>(mask, out);
}

// round 16
// speedup vs baseline: 1.4639x; 1.4639x over previous
#include <cuda_runtime.h>
#include <cuda_bf16.h>
#include <cuda_fp16.h>
#include <math.h>
#include <stdint.h>

#define B 8
#define L 2048
#define D 1024

__device__ float         g_scores[(size_t)B * L * L];
__device__ __half        g_probs[(size_t)B * L * L];
__device__ __nv_bfloat16 g_qh[(size_t)B * L * D];
__device__ __nv_bfloat16 g_ql[(size_t)B * L * D];
__device__ __nv_bfloat16 g_kh[(size_t)B * L * D];
__device__ __nv_bfloat16 g_kl[(size_t)B * L * D];
__device__ __half        g_vt[(size_t)B * L * D];   // gathered V^T: [b][d][jj]
__device__ int           g_idx[B * L];
__device__ int           g_nv[B];

#define GEMM_GRID 296   // 2 CTAs/SM * 148 SMs

// ---------------------------------------------------------------------------
__device__ __forceinline__ uint32_t smem_u32(const void* p) {
    uint32_t a;
    asm("{ .reg .u64 t; cvta.to.shared.u64 t, %1; cvt.u32.u64 %0, t; }" : "=r"(a) : "l"(p));
    return a;
}
__device__ __forceinline__ void cp16(uint32_t dst, const void* src) {
    asm volatile("cp.async.cg.shared.global [%0], [%1], 16;" :: "r"(dst), "l"(src) : "memory");
}
#define CP_COMMIT() asm volatile("cp.async.commit_group;" ::: "memory")
#define CP_WAIT(n)  asm volatile("cp.async.wait_group %0;" :: "n"(n) : "memory")

__device__ __forceinline__ void mma_bf16(float c[4], uint32_t a0, uint32_t a1,
                                         uint32_t a2, uint32_t a3,
                                         uint32_t b0, uint32_t b1) {
    asm volatile(
        "mma.sync.aligned.m16n8k16.row.col.f32.bf16.bf16.f32 "
        "{%0,%1,%2,%3}, {%4,%5,%6,%7}, {%8,%9}, {%0,%1,%2,%3};"
        : "+f"(c[0]), "+f"(c[1]), "+f"(c[2]), "+f"(c[3])
        : "r"(a0), "r"(a1), "r"(a2), "r"(a3), "r"(b0), "r"(b1));
}
__device__ __forceinline__ void mma_f16(float c[4], uint32_t a0, uint32_t a1,
                                        uint32_t a2, uint32_t a3,
                                        uint32_t b0, uint32_t b1) {
    asm volatile(
        "mma.sync.aligned.m16n8k16.row.col.f32.f16.f16.f32 "
        "{%0,%1,%2,%3}, {%4,%5,%6,%7}, {%8,%9}, {%0,%1,%2,%3};"
        : "+f"(c[0]), "+f"(c[1]), "+f"(c[2]), "+f"(c[3])
        : "r"(a0), "r"(a1), "r"(a2), "r"(a3), "r"(b0), "r"(b1));
}

// ---------------------------------------------------------------------------
// Kernel 0a: per-batch compaction of valid indices
// ---------------------------------------------------------------------------
__global__ __launch_bounds__(256) void compact_kernel(const int* __restrict__ mask)
{
    const int b = blockIdx.x;
    const int tid = threadIdx.x, lane = tid & 31, wid = tid >> 5;
    const int* mb = mask + b * L;
    __shared__ int wsum[8];

    int m[8];
    int4 a = *(const int4*)(mb + tid * 8);
    int4 c = *(const int4*)(mb + tid * 8 + 4);
    m[0]=a.x; m[1]=a.y; m[2]=a.z; m[3]=a.w;
    m[4]=c.x; m[5]=c.y; m[6]=c.z; m[7]=c.w;

    int tot = 0;
    #pragma unroll
    for (int e = 0; e < 8; e++) tot += m[e];

    int inc = tot;
    #pragma unroll
    for (int o = 1; o < 32; o <<= 1) {
        int v = __shfl_up_sync(0xffffffffu, inc, o);
        if (lane >= o) inc += v;
    }
    if (lane == 31) wsum[wid] = inc;
    __syncthreads();
    int woff = 0;
    #pragma unroll
    for (int w = 0; w < 8; w++) if (w < wid) woff += wsum[w];

    int pos = woff + inc - tot;
    #pragma unroll
    for (int e = 0; e < 8; e++)
        if (m[e]) g_idx[b * L + pos++] = tid * 8 + e;

    if (tid == 255) g_nv[b] = woff + inc;
}

// ---------------------------------------------------------------------------
// Kernel 0b: zero-fill output rows with m_i == 0 (runs last)
// ---------------------------------------------------------------------------
__global__ __launch_bounds__(256) void zerofill_kernel(
    const int* __restrict__ mask, float* __restrict__ out)
{
    const int row = blockIdx.x;
    const int b = row >> 11, i = row & (L - 1);
    if (mask[b * L + i]) return;
    float4 z = make_float4(0.f, 0.f, 0.f, 0.f);
    *(float4*)(out + ((size_t)b * L + i) * D + threadIdx.x * 4) = z;
}

// ---------------------------------------------------------------------------
// Prep 1: gather q,k valid rows -> bf16 hi/lo, k-pair-interleaved layout.
// ---------------------------------------------------------------------------
__global__ __launch_bounds__(256) void prep_qk_kernel(
    const float* __restrict__ q, const float* __restrict__ k)
{
    const float* src = blockIdx.y ? k : q;
    __nv_bfloat16* dh = blockIdx.y ? g_kh : g_qh;
    __nv_bfloat16* dl = blockIdx.y ? g_kl : g_ql;
    size_t gi = (size_t)blockIdx.x * 256 + threadIdx.x;
    const int row = (int)(gi >> 6);
    const int b = row >> 11, ii = row & (L - 1);
    if (ii >= g_nv[b]) return;
    const int gidx = g_idx[b * L + ii];
    const float* s = src + ((size_t)b * L + gidx) * D + (gi & 63) * 16;

    uint32_t h[8], l[8];
    #pragma unroll
    for (int qd = 0; qd < 4; ++qd) {
        float4 x = *(const float4*)(s + 4 * qd);
        __nv_bfloat162 h0 = __floats2bfloat162_rn(x.x, x.y);
        __nv_bfloat162 h1 = __floats2bfloat162_rn(x.z, x.w);
        float2 b0 = __bfloat1622float2(h0), b1 = __bfloat1622float2(h1);
        __nv_bfloat162 l0 = __floats2bfloat162_rn(x.x - b0.x, x.y - b0.y);
        __nv_bfloat162 l1 = __floats2bfloat162_rn(x.z - b1.x, x.w - b1.y);
        h[2*qd] = *(uint32_t*)&h0; h[2*qd+1] = *(uint32_t*)&h1;
        l[2*qd] = *(uint32_t*)&l0; l[2*qd+1] = *(uint32_t*)&l1;
    }
    *(uint4*)(dh + gi * 16)     = make_uint4(h[0], h[4], h[1], h[5]);
    *(uint4*)(dh + gi * 16 + 8) = make_uint4(h[2], h[6], h[3], h[7]);
    *(uint4*)(dl + gi * 16)     = make_uint4(l[0], l[4], l[1], l[5]);
    *(uint4*)(dl + gi * 16 + 8) = make_uint4(l[2], l[6], l[3], l[7]);
}

// ---------------------------------------------------------------------------
// Prep 2: gather V valid rows, f32 [b][j][d] -> fp16 transposed [b][d][jj].
// ---------------------------------------------------------------------------
__global__ __launch_bounds__(256) void prep_v_kernel(const float* __restrict__ v)
{
    __shared__ __half t[32][72];
    const int b = blockIdx.z, d0 = blockIdx.y * 32, j0 = blockIdx.x * 64;
    const int nv = g_nv[b];
    const int tid = threadIdx.x;
    const int dd = tid & 31, jw = tid >> 5;
    #pragma unroll
    for (int it = 0; it < 8; ++it) {
        int jj = jw + it * 8;
        int jg = j0 + jj;
        float x = 0.0f;
        if (jg < nv) x = v[((size_t)b * L + g_idx[b * L + jg]) * D + d0 + dd];
        t[dd][jj] = __float2half_rn(x);
    }
    __syncthreads();
    const int row = tid >> 3, c8 = (tid & 7) * 8;
    uint32_t u[4];
    #pragma unroll
    for (int e = 0; e < 4; ++e) {
        __half2 hp; hp.x = t[row][c8 + 2*e]; hp.y = t[row][c8 + 2*e + 1];
        u[e] = *(uint32_t*)&hp;
    }
    *(uint4*)(g_vt + ((size_t)b * D + d0 + row) * L + j0 + c8) =
        make_uint4(u[0], u[1], u[2], u[3]);
}

// ---------------------------------------------------------------------------
// Kernel 1: compacted S = Qc Kc^T, bf16 3-term split. (R14, best measured)
// 128 threads (4 warps, 2x2), warp tile 64x64, BK=32, 2-stage, 2 CTAs/SM.
// ---------------------------------------------------------------------------
#define QK_RS    96
#define QK_TILE  (128 * QK_RS)
#define QK_STAGE (4 * QK_TILE)       // 49152
#define QK_NC    (D / 32)

__global__ __launch_bounds__(128, 2) void qk_kernel()
{
    extern __shared__ char sm[];
    const uint32_t smbase = smem_u32(sm);
    const int tid = threadIdx.x, lane = tid & 31, wid = tid >> 5;
    const int g = lane >> 2, t = lane & 3;
    const int rm = (wid >> 1) * 64, rn = (wid & 1) * 64;

    int ntl[8], pre[9];
    pre[0] = 0;
    #pragma unroll
    for (int bb = 0; bb < 8; ++bb) {
        ntl[bb] = (g_nv[bb] + 127) >> 7;
        pre[bb + 1] = pre[bb] + ntl[bb] * ntl[bb];
    }
    const int total = pre[8];

    for (int tile = blockIdx.x; tile < total; tile += GEMM_GRID) {
        int b = 0;
        #pragma unroll
        for (int bb = 0; bb < 8; ++bb) if (tile >= pre[bb + 1]) b = bb + 1;
        const int loc = tile - pre[b];
        const int nt = ntl[b];
        const int ty = loc / nt, tx = loc - ty * nt;
        const int ti = ty * 128, tj = tx * 128;

        const __nv_bfloat16* qh = g_qh + ((size_t)b * L + ti) * D;
        const __nv_bfloat16* ql = g_ql + ((size_t)b * L + ti) * D;
        const __nv_bfloat16* kh = g_kh + ((size_t)b * L + tj) * D;
        const __nv_bfloat16* kl = g_kl + ((size_t)b * L + tj) * D;

        float acc[4][8][4];
        #pragma unroll
        for (int a = 0; a < 4; a++)
            #pragma unroll
            for (int bb = 0; bb < 8; bb++)
                #pragma unroll
                for (int cc = 0; cc < 4; cc++) acc[a][bb][cc] = 0.0f;

        #define QK_LOAD(c, st) do { \
            uint32_t sb = smbase + (st) * QK_STAGE; \
            _Pragma("unroll") \
            for (int e = 0; e < 16; ++e) { \
                const int tl = e >> 2; \
                const __nv_bfloat16* gs = (tl == 0) ? qh : (tl == 1) ? ql \
                                        : (tl == 2) ? kh : kl; \
                int rc = (e & 3) * 128 + tid; \
                int r = rc >> 2, sg = rc & 3; \
                uint32_t doff = (uint32_t)tl * QK_TILE + (uint32_t)r * QK_RS + sg * 16; \
                size_t goff = (size_t)r * D + (size_t)(c) * 32 + sg * 8; \
                cp16(sb + doff, gs + goff); \
            } } while (0)

        #define QK_COMPUTE(buf) do { \
            const char* Qh_ = sm + (buf) * QK_STAGE; \
            const char* Ql_ = Qh_ + QK_TILE; \
            const char* Kh_ = Qh_ + 2 * QK_TILE; \
            const char* Kl_ = Qh_ + 3 * QK_TILE; \
            _Pragma("unroll") \
            for (int s = 0; s < 2; ++s) { \
                const uint32_t so = (uint32_t)(s * 32 + t * 8); \
                uint2 ah[4][2], al[4][2], bh[8], bl[8]; \
                _Pragma("unroll") \
                for (int mt = 0; mt < 4; ++mt) { \
                    uint32_t r0 = (uint32_t)(rm + mt * 16 + g) * QK_RS + so; \
                    ah[mt][0] = *(const uint2*)(Qh_ + r0); \
                    ah[mt][1] = *(const uint2*)(Qh_ + r0 + 8 * QK_RS); \
                    al[mt][0] = *(const uint2*)(Ql_ + r0); \
                    al[mt][1] = *(const uint2*)(Ql_ + r0 + 8 * QK_RS); \
                } \
                _Pragma("unroll") \
                for (int nt2 = 0; nt2 < 8; ++nt2) { \
                    uint32_t rb = (uint32_t)(rn + nt2 * 8 + g) * QK_RS + so; \
                    bh[nt2] = *(const uint2*)(Kh_ + rb); \
                    bl[nt2] = *(const uint2*)(Kl_ + rb); \
                } \
                _Pragma("unroll") \
                for (int nt2 = 0; nt2 < 8; ++nt2) \
                    _Pragma("unroll") \
                    for (int mt = 0; mt < 4; ++mt) \
                        mma_bf16(acc[mt][nt2], ah[mt][0].x, ah[mt][1].x, ah[mt][0].y, ah[mt][1].y, bh[nt2].x, bh[nt2].y); \
                _Pragma("unroll") \
                for (int nt2 = 0; nt2 < 8; ++nt2) \
                    _Pragma("unroll") \
                    for (int mt = 0; mt < 4; ++mt) \
                        mma_bf16(acc[mt][nt2], ah[mt][0].x, ah[mt][1].x, ah[mt][0].y, ah[mt][1].y, bl[nt2].x, bl[nt2].y); \
                _Pragma("unroll") \
                for (int nt2 = 0; nt2 < 8; ++nt2) \
                    _Pragma("unroll") \
                    for (int mt = 0; mt < 4; ++mt) \
                        mma_bf16(acc[mt][nt2], al[mt][0].x, al[mt][1].x, al[mt][0].y, al[mt][1].y, bh[nt2].x, bh[nt2].y); \
            } } while (0)

        QK_LOAD(0, 0); CP_COMMIT();
        for (int c = 0; c < QK_NC; ++c) {
            CP_WAIT(0);
            __syncthreads();
            if (c + 1 < QK_NC) { QK_LOAD(c + 1, (c + 1) & 1); CP_COMMIT(); }
            QK_COMPUTE(c & 1);
        }

        #pragma unroll
        for (int mt = 0; mt < 4; ++mt) {
            int r0 = rm + mt * 16 + g;
            float* row0 = g_scores + ((size_t)b * L + ti + r0) * L + tj;
            float* row1 = row0 + (size_t)8 * L;
            #pragma unroll
            for (int nt2 = 0; nt2 < 8; ++nt2) {
                int c0 = rn + nt2 * 8 + 2 * t;
                *(float2*)(row0 + c0) = make_float2(acc[mt][nt2][0], acc[mt][nt2][1]);
                *(float2*)(row1 + c0) = make_float2(acc[mt][nt2][2], acc[mt][nt2][3]);
            }
        }
        __syncthreads();
    }
}

// ---------------------------------------------------------------------------
// Kernel 2: softmax over compacted row (length nv).
// ---------------------------------------------------------------------------
__global__ __launch_bounds__(256) void rowstats_kernel()
{
    const int row = blockIdx.x;
    const int b = row >> 11;
    const int ii = row & (L - 1);
    const int nv = g_nv[b];
    if (ii >= nv) return;
    const float* s = g_scores + (size_t)row * L;
    const int tid = threadIdx.x;
    const int base = tid * 8;

    float vv[8];
    if (base + 8 <= nv) {
        float4 v0 = *(const float4*)(s + base);
        float4 v1 = *(const float4*)(s + base + 4);
        vv[0]=v0.x; vv[1]=v0.y; vv[2]=v0.z; vv[3]=v0.w;
        vv[4]=v1.x; vv[5]=v1.y; vv[6]=v1.z; vv[7]=v1.w;
    } else {
        #pragma unroll
        for (int e = 0; e < 8; e++)
            vv[e] = (base + e < nv) ? s[base + e] : -INFINITY;
    }

    __shared__ float sredA[8], sredB[8];
    const unsigned full = 0xffffffffu;

    float lmax = vv[0];
    #pragma unroll
    for (int e = 1; e < 8; e++) lmax = fmaxf(lmax, vv[e]);
    #pragma unroll
    for (int o = 16; o > 0; o >>= 1) lmax = fmaxf(lmax, __shfl_xor_sync(full, lmax, o));
    if ((tid & 31) == 0) sredA[tid >> 5] = lmax;
    __syncthreads();
    float bmax = sredA[0];
    #pragma unroll
    for (int w = 1; w < 8; w++) bmax = fmaxf(bmax, sredA[w]);
    if (nv < L) bmax = fmaxf(bmax, 0.0f);

    float p[8];
    float lsum = 0.0f;
    #pragma unroll
    for (int e = 0; e < 8; e++) { p[e] = __expf(vv[e] - bmax); lsum += p[e]; }
    #pragma unroll
    for (int o = 16; o > 0; o >>= 1) lsum += __shfl_xor_sync(full, lsum, o);
    if ((tid & 31) == 0) sredB[tid >> 5] = lsum;
    __syncthreads();
    float bsum = 0.0f;
    #pragma unroll
    for (int w = 0; w < 8; w++) bsum += sredB[w];

    const float denom = bsum + ((bsum == 0.0f) ? 1.0f : 0.0f) + 1e-20f;
    const float scale = 1.0f / denom;

    const int ncpad = ((nv + 63) >> 6) << 6;
    if (base < ncpad) {
        uint32_t u[4];
        #pragma unroll
        for (int e = 0; e < 4; ++e) {
            __half2 hp = __floats2half2_rn(p[2*e] * scale, p[2*e+1] * scale);
            u[e] = *(uint32_t*)&hp;
        }
        *(uint4*)(g_probs + (size_t)row * L + base) = make_uint4(u[0], u[1], u[2], u[3]);
    }
}

// ---------------------------------------------------------------------------
// Kernel 3: Oc = Pc Vc (fp16 mma). 128 thr, 4 warps 2x2, warp tile 64x64,
// BK=64, 2 stages, 2 CTAs/SM (no reg cap pressure), dense tile scheduling.
// ---------------------------------------------------------------------------
#define PV_RS    144
#define PV_TILE  (128 * PV_RS)       // 18432
#define PV_STAGE (2 * PV_TILE)       // 36864

__global__ __launch_bounds__(128, 2) void pv_kernel(float* __restrict__ out)
{
    extern __shared__ char sm[];
    const uint32_t smbase = smem_u32(sm);
    const int tid = threadIdx.x, lane = tid & 31, wid = tid >> 5;
    const int g = lane >> 2, t = lane & 3;
    const int rm = (wid >> 1) * 64, rn = (wid & 1) * 64;

    int ntl[8], pre[9];
    pre[0] = 0;
    #pragma unroll
    for (int bb = 0; bb < 8; ++bb) {
        ntl[bb] = (g_nv[bb] + 127) >> 7;
        pre[bb + 1] = pre[bb] + ntl[bb] * 8;
    }
    const int total = pre[8];

    for (int tile = blockIdx.x; tile < total; tile += GEMM_GRID) {
        int b = 0;
        #pragma unroll
        for (int bb = 0; bb < 8; ++bb) if (tile >= pre[bb + 1]) b = bb + 1;
        const int loc = tile - pre[b];
        const int ty = loc >> 3, txd = loc & 7;
        const int ti = ty * 128, td = txd * 128;
        const int nv = g_nv[b];
        const int NC = (nv + 63) >> 6;

        const __half* pb  = g_probs + ((size_t)b * L + ti) * L;
        const __half* vtb = g_vt + ((size_t)b * D + td) * L;

        float acc[4][8][4];
        #pragma unroll
        for (int a = 0; a < 4; a++)
            #pragma unroll
            for (int bb = 0; bb < 8; bb++)
                #pragma unroll
                for (int cc = 0; cc < 4; cc++) acc[a][bb][cc] = 0.0f;

        #define PV_LOAD(c, st) do { \
            uint32_t sb = smbase + (st) * PV_STAGE; \
            _Pragma("unroll") \
            for (int e = 0; e < 16; ++e) { \
                const int tl = e >> 3; \
                int rc = (e & 7) * 128 + tid; \
                int r = rc >> 3, cg = rc & 7; \
                uint32_t doff = (uint32_t)tl * PV_TILE + (uint32_t)r * PV_RS + cg * 16; \
                size_t goff = (size_t)r * L + (size_t)(c) * 64 + cg * 8; \
                cp16(sb + doff, (tl ? vtb : pb) + goff); \
            } } while (0)

        #define PV_COMPUTE(buf) do { \
            const char* Pt = sm + (buf) * PV_STAGE; \
            const char* Vt = Pt + PV_TILE; \
            _Pragma("unroll") \
            for (int s = 0; s < 4; ++s) { \
                const uint32_t so = (uint32_t)(32 * s + 4 * t); \
                uint32_t a0[4], a1[4], a2[4], a3[4]; \
                _Pragma("unroll") \
                for (int mt = 0; mt < 4; ++mt) { \
                    uint32_t r0 = (uint32_t)(rm + mt * 16 + g) * PV_RS + so; \
                    a0[mt] = *(const uint32_t*)(Pt + r0); \
                    a2[mt] = *(const uint32_t*)(Pt + r0 + 16); \
                    a1[mt] = *(const uint32_t*)(Pt + r0 + 8 * PV_RS); \
                    a3[mt] = *(const uint32_t*)(Pt + r0 + 8 * PV_RS + 16); \
                } \
                _Pragma("unroll") \
                for (int nt2 = 0; nt2 < 8; ++nt2) { \
                    uint32_t rb = (uint32_t)(rn + nt2 * 8 + g) * PV_RS + so; \
                    uint32_t b0 = *(const uint32_t*)(Vt + rb); \
                    uint32_t b1 = *(const uint32_t*)(Vt + rb + 16); \
                    _Pragma("unroll") \
                    for (int mt = 0; mt < 4; ++mt) \
                        mma_f16(acc[mt][nt2], a0[mt], a1[mt], a2[mt], a3[mt], b0, b1); \
                } \
            } } while (0)

        PV_LOAD(0, 0); CP_COMMIT();
        for (int c = 0; c < NC; ++c) {
            CP_WAIT(0);
            __syncthreads();
            if (c + 1 < NC) { PV_LOAD(c + 1, (c + 1) & 1); CP_COMMIT(); }
            PV_COMPUTE(c & 1);
        }

        const int* idxb = g_idx + b * L;
        #pragma unroll
        for (int mt = 0; mt < 4; ++mt) {
            int r0 = rm + mt * 16 + g;
            int i0 = ti + r0, i1 = i0 + 8;
            #pragma unroll
            for (int half = 0; half < 2; ++half) {
                int irow = half ? i1 : i0;
                if (irow < nv) {
                    float* orow = out + ((size_t)b * L + idxb[irow]) * D + td;
                    #pragma unroll
                    for (int nt2 = 0; nt2 < 8; ++nt2) {
                        int c0 = rn + nt2 * 8 + 2 * t;
                        *(float2*)(orow + c0) = half
                            ? make_float2(acc[mt][nt2][2], acc[mt][nt2][3])
                            : make_float2(acc[mt][nt2][0], acc[mt][nt2][1]);
                    }
                }
            }
        }
        __syncthreads();
    }
}

// ---------------------------------------------------------------------------
extern "C" void kernel_launch(void* const* d_in, const int* in_sizes, int n_in,
                              void* d_out, int out_size)
{
    const float* q    = (const float*)d_in[0];
    const float* k    = (const float*)d_in[1];
    const float* v    = (const float*)d_in[2];
    const int*   mask = (const int*)d_in[3];
    float*       out  = (float*)d_out;

    cudaFuncSetAttribute(qk_kernel, cudaFuncAttributeMaxDynamicSharedMemorySize, 2 * QK_STAGE);
    cudaFuncSetAttribute(pv_kernel, cudaFuncAttributeMaxDynamicSharedMemorySize, 2 * PV_STAGE);

    compact_kernel<<<B, 256>>>(mask);
    prep_qk_kernel<<<dim3((B * L * D / 16) / 256, 2, 1), 256>>>(q, k);
    prep_v_kernel<<<dim3(L / 64, D / 32, B), 256>>>(v);

    qk_kernel<<<GEMM_GRID, 128, 2 * QK_STAGE>>>();   // slot #4 -> ncu sample

    rowstats_kernel<<<B * L, 256>>>();

    pv_kernel<<<GEMM_GRID, 128, 2 * PV_STAGE>>>(out);

    zerofill_kernel<<<B * L, 256>>>(mask, out);
}

// round 17
// speedup vs baseline: 1.4724x; 1.0058x over previous
#include <cuda_runtime.h>
#include <cuda_bf16.h>
#include <cuda_fp16.h>
#include <math.h>
#include <stdint.h>

#define B 8
#define L 2048
#define D 1024

__device__ float         g_scores[(size_t)B * L * L];
__device__ __half        g_probs[(size_t)B * L * L];
__device__ __nv_bfloat16 g_qh[(size_t)B * L * D];
__device__ __nv_bfloat16 g_ql[(size_t)B * L * D];
__device__ __nv_bfloat16 g_kh[(size_t)B * L * D];
__device__ __nv_bfloat16 g_kl[(size_t)B * L * D];
__device__ __half        g_vt[(size_t)B * L * D];   // gathered V^T: [b][d][jj]
__device__ int           g_idx[B * L];
__device__ int           g_nv[B];

#define GEMM_GRID 296   // 2 CTAs/SM * 148 SMs

// ---------------------------------------------------------------------------
__device__ __forceinline__ uint32_t smem_u32(const void* p) {
    uint32_t a;
    asm("{ .reg .u64 t; cvta.to.shared.u64 t, %1; cvt.u32.u64 %0, t; }" : "=r"(a) : "l"(p));
    return a;
}
__device__ __forceinline__ void cp16(uint32_t dst, const void* src) {
    asm volatile("cp.async.cg.shared.global [%0], [%1], 16;" :: "r"(dst), "l"(src) : "memory");
}
#define CP_COMMIT() asm volatile("cp.async.commit_group;" ::: "memory")
#define CP_WAIT(n)  asm volatile("cp.async.wait_group %0;" :: "n"(n) : "memory")

__device__ __forceinline__ void mma_bf16(float c[4], uint32_t a0, uint32_t a1,
                                         uint32_t a2, uint32_t a3,
                                         uint32_t b0, uint32_t b1) {
    asm volatile(
        "mma.sync.aligned.m16n8k16.row.col.f32.bf16.bf16.f32 "
        "{%0,%1,%2,%3}, {%4,%5,%6,%7}, {%8,%9}, {%0,%1,%2,%3};"
        : "+f"(c[0]), "+f"(c[1]), "+f"(c[2]), "+f"(c[3])
        : "r"(a0), "r"(a1), "r"(a2), "r"(a3), "r"(b0), "r"(b1));
}
__device__ __forceinline__ void mma_f16(float c[4], uint32_t a0, uint32_t a1,
                                        uint32_t a2, uint32_t a3,
                                        uint32_t b0, uint32_t b1) {
    asm volatile(
        "mma.sync.aligned.m16n8k16.row.col.f32.f16.f16.f32 "
        "{%0,%1,%2,%3}, {%4,%5,%6,%7}, {%8,%9}, {%0,%1,%2,%3};"
        : "+f"(c[0]), "+f"(c[1]), "+f"(c[2]), "+f"(c[3])
        : "r"(a0), "r"(a1), "r"(a2), "r"(a3), "r"(b0), "r"(b1));
}

// ---------------------------------------------------------------------------
// Kernel 0a: per-batch compaction of valid indices
// ---------------------------------------------------------------------------
__global__ __launch_bounds__(256) void compact_kernel(const int* __restrict__ mask)
{
    const int b = blockIdx.x;
    const int tid = threadIdx.x, lane = tid & 31, wid = tid >> 5;
    const int* mb = mask + b * L;
    __shared__ int wsum[8];

    int m[8];
    int4 a = *(const int4*)(mb + tid * 8);
    int4 c = *(const int4*)(mb + tid * 8 + 4);
    m[0]=a.x; m[1]=a.y; m[2]=a.z; m[3]=a.w;
    m[4]=c.x; m[5]=c.y; m[6]=c.z; m[7]=c.w;

    int tot = 0;
    #pragma unroll
    for (int e = 0; e < 8; e++) tot += m[e];

    int inc = tot;
    #pragma unroll
    for (int o = 1; o < 32; o <<= 1) {
        int v = __shfl_up_sync(0xffffffffu, inc, o);
        if (lane >= o) inc += v;
    }
    if (lane == 31) wsum[wid] = inc;
    __syncthreads();
    int woff = 0;
    #pragma unroll
    for (int w = 0; w < 8; w++) if (w < wid) woff += wsum[w];

    int pos = woff + inc - tot;
    #pragma unroll
    for (int e = 0; e < 8; e++)
        if (m[e]) g_idx[b * L + pos++] = tid * 8 + e;

    if (tid == 255) g_nv[b] = woff + inc;
}

// ---------------------------------------------------------------------------
// Kernel 0b: zero-fill output rows with m_i == 0 (runs last)
// ---------------------------------------------------------------------------
__global__ __launch_bounds__(256) void zerofill_kernel(
    const int* __restrict__ mask, float* __restrict__ out)
{
    const int row = blockIdx.x;
    const int b = row >> 11, i = row & (L - 1);
    if (mask[b * L + i]) return;
    float4 z = make_float4(0.f, 0.f, 0.f, 0.f);
    *(float4*)(out + ((size_t)b * L + i) * D + threadIdx.x * 4) = z;
}

// ---------------------------------------------------------------------------
// Prep 1: gather q,k valid rows -> bf16 hi/lo, k-pair-interleaved layout.
// ---------------------------------------------------------------------------
__global__ __launch_bounds__(256) void prep_qk_kernel(
    const float* __restrict__ q, const float* __restrict__ k)
{
    const float* src = blockIdx.y ? k : q;
    __nv_bfloat16* dh = blockIdx.y ? g_kh : g_qh;
    __nv_bfloat16* dl = blockIdx.y ? g_kl : g_ql;
    size_t gi = (size_t)blockIdx.x * 256 + threadIdx.x;
    const int row = (int)(gi >> 6);
    const int b = row >> 11, ii = row & (L - 1);
    if (ii >= g_nv[b]) return;
    const int gidx = g_idx[b * L + ii];
    const float* s = src + ((size_t)b * L + gidx) * D + (gi & 63) * 16;

    uint32_t h[8], l[8];
    #pragma unroll
    for (int qd = 0; qd < 4; ++qd) {
        float4 x = *(const float4*)(s + 4 * qd);
        __nv_bfloat162 h0 = __floats2bfloat162_rn(x.x, x.y);
        __nv_bfloat162 h1 = __floats2bfloat162_rn(x.z, x.w);
        float2 b0 = __bfloat1622float2(h0), b1 = __bfloat1622float2(h1);
        __nv_bfloat162 l0 = __floats2bfloat162_rn(x.x - b0.x, x.y - b0.y);
        __nv_bfloat162 l1 = __floats2bfloat162_rn(x.z - b1.x, x.w - b1.y);
        h[2*qd] = *(uint32_t*)&h0; h[2*qd+1] = *(uint32_t*)&h1;
        l[2*qd] = *(uint32_t*)&l0; l[2*qd+1] = *(uint32_t*)&l1;
    }
    *(uint4*)(dh + gi * 16)     = make_uint4(h[0], h[4], h[1], h[5]);
    *(uint4*)(dh + gi * 16 + 8) = make_uint4(h[2], h[6], h[3], h[7]);
    *(uint4*)(dl + gi * 16)     = make_uint4(l[0], l[4], l[1], l[5]);
    *(uint4*)(dl + gi * 16 + 8) = make_uint4(l[2], l[6], l[3], l[7]);
}

// ---------------------------------------------------------------------------
// Prep 2: gather V valid rows, f32 [b][j][d] -> fp16 transposed [b][d][jj].
// ---------------------------------------------------------------------------
__global__ __launch_bounds__(256) void prep_v_kernel(const float* __restrict__ v)
{
    __shared__ __half t[32][72];
    const int b = blockIdx.z, d0 = blockIdx.y * 32, j0 = blockIdx.x * 64;
    const int nv = g_nv[b];
    const int tid = threadIdx.x;
    const int dd = tid & 31, jw = tid >> 5;
    #pragma unroll
    for (int it = 0; it < 8; ++it) {
        int jj = jw + it * 8;
        int jg = j0 + jj;
        float x = 0.0f;
        if (jg < nv) x = v[((size_t)b * L + g_idx[b * L + jg]) * D + d0 + dd];
        t[dd][jj] = __float2half_rn(x);
    }
    __syncthreads();
    const int row = tid >> 3, c8 = (tid & 7) * 8;
    uint32_t u[4];
    #pragma unroll
    for (int e = 0; e < 4; ++e) {
        __half2 hp; hp.x = t[row][c8 + 2*e]; hp.y = t[row][c8 + 2*e + 1];
        u[e] = *(uint32_t*)&hp;
    }
    *(uint4*)(g_vt + ((size_t)b * D + d0 + row) * L + j0 + c8) =
        make_uint4(u[0], u[1], u[2], u[3]);
}

// ---------------------------------------------------------------------------
// Kernel 1: compacted S = Qc Kc^T, bf16 3-term split. (R14/R16, best measured)
// 128 threads (4 warps, 2x2), warp tile 64x64, BK=32, 2-stage, 2 CTAs/SM.
// ---------------------------------------------------------------------------
#define QK_RS    96
#define QK_TILE  (128 * QK_RS)
#define QK_STAGE (4 * QK_TILE)       // 49152
#define QK_NC    (D / 32)

__global__ __launch_bounds__(128, 2) void qk_kernel()
{
    extern __shared__ char sm[];
    const uint32_t smbase = smem_u32(sm);
    const int tid = threadIdx.x, lane = tid & 31, wid = tid >> 5;
    const int g = lane >> 2, t = lane & 3;
    const int rm = (wid >> 1) * 64, rn = (wid & 1) * 64;

    int ntl[8], pre[9];
    pre[0] = 0;
    #pragma unroll
    for (int bb = 0; bb < 8; ++bb) {
        ntl[bb] = (g_nv[bb] + 127) >> 7;
        pre[bb + 1] = pre[bb] + ntl[bb] * ntl[bb];
    }
    const int total = pre[8];

    for (int tile = blockIdx.x; tile < total; tile += GEMM_GRID) {
        int b = 0;
        #pragma unroll
        for (int bb = 0; bb < 8; ++bb) if (tile >= pre[bb + 1]) b = bb + 1;
        const int loc = tile - pre[b];
        const int nt = ntl[b];
        const int ty = loc / nt, tx = loc - ty * nt;
        const int ti = ty * 128, tj = tx * 128;

        const __nv_bfloat16* qh = g_qh + ((size_t)b * L + ti) * D;
        const __nv_bfloat16* ql = g_ql + ((size_t)b * L + ti) * D;
        const __nv_bfloat16* kh = g_kh + ((size_t)b * L + tj) * D;
        const __nv_bfloat16* kl = g_kl + ((size_t)b * L + tj) * D;

        float acc[4][8][4];
        #pragma unroll
        for (int a = 0; a < 4; a++)
            #pragma unroll
            for (int bb = 0; bb < 8; bb++)
                #pragma unroll
                for (int cc = 0; cc < 4; cc++) acc[a][bb][cc] = 0.0f;

        #define QK_LOAD(c, st) do { \
            uint32_t sb = smbase + (st) * QK_STAGE; \
            _Pragma("unroll") \
            for (int e = 0; e < 16; ++e) { \
                const int tl = e >> 2; \
                const __nv_bfloat16* gs = (tl == 0) ? qh : (tl == 1) ? ql \
                                        : (tl == 2) ? kh : kl; \
                int rc = (e & 3) * 128 + tid; \
                int r = rc >> 2, sg = rc & 3; \
                uint32_t doff = (uint32_t)tl * QK_TILE + (uint32_t)r * QK_RS + sg * 16; \
                size_t goff = (size_t)r * D + (size_t)(c) * 32 + sg * 8; \
                cp16(sb + doff, gs + goff); \
            } } while (0)

        #define QK_COMPUTE(buf) do { \
            const char* Qh_ = sm + (buf) * QK_STAGE; \
            const char* Ql_ = Qh_ + QK_TILE; \
            const char* Kh_ = Qh_ + 2 * QK_TILE; \
            const char* Kl_ = Qh_ + 3 * QK_TILE; \
            _Pragma("unroll") \
            for (int s = 0; s < 2; ++s) { \
                const uint32_t so = (uint32_t)(s * 32 + t * 8); \
                uint2 ah[4][2], al[4][2], bh[8], bl[8]; \
                _Pragma("unroll") \
                for (int mt = 0; mt < 4; ++mt) { \
                    uint32_t r0 = (uint32_t)(rm + mt * 16 + g) * QK_RS + so; \
                    ah[mt][0] = *(const uint2*)(Qh_ + r0); \
                    ah[mt][1] = *(const uint2*)(Qh_ + r0 + 8 * QK_RS); \
                    al[mt][0] = *(const uint2*)(Ql_ + r0); \
                    al[mt][1] = *(const uint2*)(Ql_ + r0 + 8 * QK_RS); \
                } \
                _Pragma("unroll") \
                for (int nt2 = 0; nt2 < 8; ++nt2) { \
                    uint32_t rb = (uint32_t)(rn + nt2 * 8 + g) * QK_RS + so; \
                    bh[nt2] = *(const uint2*)(Kh_ + rb); \
                    bl[nt2] = *(const uint2*)(Kl_ + rb); \
                } \
                _Pragma("unroll") \
                for (int nt2 = 0; nt2 < 8; ++nt2) \
                    _Pragma("unroll") \
                    for (int mt = 0; mt < 4; ++mt) \
                        mma_bf16(acc[mt][nt2], ah[mt][0].x, ah[mt][1].x, ah[mt][0].y, ah[mt][1].y, bh[nt2].x, bh[nt2].y); \
                _Pragma("unroll") \
                for (int nt2 = 0; nt2 < 8; ++nt2) \
                    _Pragma("unroll") \
                    for (int mt = 0; mt < 4; ++mt) \
                        mma_bf16(acc[mt][nt2], ah[mt][0].x, ah[mt][1].x, ah[mt][0].y, ah[mt][1].y, bl[nt2].x, bl[nt2].y); \
                _Pragma("unroll") \
                for (int nt2 = 0; nt2 < 8; ++nt2) \
                    _Pragma("unroll") \
                    for (int mt = 0; mt < 4; ++mt) \
                        mma_bf16(acc[mt][nt2], al[mt][0].x, al[mt][1].x, al[mt][0].y, al[mt][1].y, bh[nt2].x, bh[nt2].y); \
            } } while (0)

        QK_LOAD(0, 0); CP_COMMIT();
        for (int c = 0; c < QK_NC; ++c) {
            CP_WAIT(0);
            __syncthreads();
            if (c + 1 < QK_NC) { QK_LOAD(c + 1, (c + 1) & 1); CP_COMMIT(); }
            QK_COMPUTE(c & 1);
        }

        #pragma unroll
        for (int mt = 0; mt < 4; ++mt) {
            int r0 = rm + mt * 16 + g;
            float* row0 = g_scores + ((size_t)b * L + ti + r0) * L + tj;
            float* row1 = row0 + (size_t)8 * L;
            #pragma unroll
            for (int nt2 = 0; nt2 < 8; ++nt2) {
                int c0 = rn + nt2 * 8 + 2 * t;
                *(float2*)(row0 + c0) = make_float2(acc[mt][nt2][0], acc[mt][nt2][1]);
                *(float2*)(row1 + c0) = make_float2(acc[mt][nt2][2], acc[mt][nt2][3]);
            }
        }
        __syncthreads();
    }
}

// ---------------------------------------------------------------------------
// Kernel 2: softmax over compacted row (length nv).
// ---------------------------------------------------------------------------
__global__ __launch_bounds__(256) void rowstats_kernel()
{
    const int row = blockIdx.x;
    const int b = row >> 11;
    const int ii = row & (L - 1);
    const int nv = g_nv[b];
    if (ii >= nv) return;
    const float* s = g_scores + (size_t)row * L;
    const int tid = threadIdx.x;
    const int base = tid * 8;

    float vv[8];
    if (base + 8 <= nv) {
        float4 v0 = *(const float4*)(s + base);
        float4 v1 = *(const float4*)(s + base + 4);
        vv[0]=v0.x; vv[1]=v0.y; vv[2]=v0.z; vv[3]=v0.w;
        vv[4]=v1.x; vv[5]=v1.y; vv[6]=v1.z; vv[7]=v1.w;
    } else {
        #pragma unroll
        for (int e = 0; e < 8; e++)
            vv[e] = (base + e < nv) ? s[base + e] : -INFINITY;
    }

    __shared__ float sredA[8], sredB[8];
    const unsigned full = 0xffffffffu;

    float lmax = vv[0];
    #pragma unroll
    for (int e = 1; e < 8; e++) lmax = fmaxf(lmax, vv[e]);
    #pragma unroll
    for (int o = 16; o > 0; o >>= 1) lmax = fmaxf(lmax, __shfl_xor_sync(full, lmax, o));
    if ((tid & 31) == 0) sredA[tid >> 5] = lmax;
    __syncthreads();
    float bmax = sredA[0];
    #pragma unroll
    for (int w = 1; w < 8; w++) bmax = fmaxf(bmax, sredA[w]);
    if (nv < L) bmax = fmaxf(bmax, 0.0f);

    float p[8];
    float lsum = 0.0f;
    #pragma unroll
    for (int e = 0; e < 8; e++) { p[e] = __expf(vv[e] - bmax); lsum += p[e]; }
    #pragma unroll
    for (int o = 16; o > 0; o >>= 1) lsum += __shfl_xor_sync(full, lsum, o);
    if ((tid & 31) == 0) sredB[tid >> 5] = lsum;
    __syncthreads();
    float bsum = 0.0f;
    #pragma unroll
    for (int w = 0; w < 8; w++) bsum += sredB[w];

    const float denom = bsum + ((bsum == 0.0f) ? 1.0f : 0.0f) + 1e-20f;
    const float scale = 1.0f / denom;

    const int ncpad = ((nv + 63) >> 6) << 6;
    if (base < ncpad) {
        uint32_t u[4];
        #pragma unroll
        for (int e = 0; e < 4; ++e) {
            __half2 hp = __floats2half2_rn(p[2*e] * scale, p[2*e+1] * scale);
            u[e] = *(uint32_t*)&hp;
        }
        *(uint4*)(g_probs + (size_t)row * L + base) = make_uint4(u[0], u[1], u[2], u[3]);
    }
}

// ---------------------------------------------------------------------------
// Kernel 3: Oc = Pc Vc (fp16 mma). 128 thr, 4 warps 2x2, warp tile 64x64,
// BK=64, 3-stage cp.async with wait_group(1), 2 CTAs/SM, dense scheduling.
// ---------------------------------------------------------------------------
#define PV_RS    144
#define PV_TILE  (128 * PV_RS)       // 18432
#define PV_STAGE (2 * PV_TILE)       // 36864

__global__ __launch_bounds__(128, 2) void pv_kernel(float* __restrict__ out)
{
    extern __shared__ char sm[];
    const uint32_t smbase = smem_u32(sm);
    const int tid = threadIdx.x, lane = tid & 31, wid = tid >> 5;
    const int g = lane >> 2, t = lane & 3;
    const int rm = (wid >> 1) * 64, rn = (wid & 1) * 64;

    int ntl[8], pre[9];
    pre[0] = 0;
    #pragma unroll
    for (int bb = 0; bb < 8; ++bb) {
        ntl[bb] = (g_nv[bb] + 127) >> 7;
        pre[bb + 1] = pre[bb] + ntl[bb] * 8;
    }
    const int total = pre[8];

    for (int tile = blockIdx.x; tile < total; tile += GEMM_GRID) {
        int b = 0;
        #pragma unroll
        for (int bb = 0; bb < 8; ++bb) if (tile >= pre[bb + 1]) b = bb + 1;
        const int loc = tile - pre[b];
        const int ty = loc >> 3, txd = loc & 7;
        const int ti = ty * 128, td = txd * 128;
        const int nv = g_nv[b];
        const int NC = (nv + 63) >> 6;

        const __half* pb  = g_probs + ((size_t)b * L + ti) * L;
        const __half* vtb = g_vt + ((size_t)b * D + td) * L;

        float acc[4][8][4];
        #pragma unroll
        for (int a = 0; a < 4; a++)
            #pragma unroll
            for (int bb = 0; bb < 8; bb++)
                #pragma unroll
                for (int cc = 0; cc < 4; cc++) acc[a][bb][cc] = 0.0f;

        #define PV_LOAD(c, st) do { \
            uint32_t sb = smbase + (st) * PV_STAGE; \
            _Pragma("unroll") \
            for (int e = 0; e < 16; ++e) { \
                const int tl = e >> 3; \
                int rc = (e & 7) * 128 + tid; \
                int r = rc >> 3, cg = rc & 7; \
                uint32_t doff = (uint32_t)tl * PV_TILE + (uint32_t)r * PV_RS + cg * 16; \
                size_t goff = (size_t)r * L + (size_t)(c) * 64 + cg * 8; \
                cp16(sb + doff, (tl ? vtb : pb) + goff); \
            } } while (0)

        #define PV_COMPUTE(buf) do { \
            const char* Pt = sm + (buf) * PV_STAGE; \
            const char* Vt = Pt + PV_TILE; \
            _Pragma("unroll") \
            for (int s = 0; s < 4; ++s) { \
                const uint32_t so = (uint32_t)(32 * s + 4 * t); \
                uint32_t a0[4], a1[4], a2[4], a3[4]; \
                _Pragma("unroll") \
                for (int mt = 0; mt < 4; ++mt) { \
                    uint32_t r0 = (uint32_t)(rm + mt * 16 + g) * PV_RS + so; \
                    a0[mt] = *(const uint32_t*)(Pt + r0); \
                    a2[mt] = *(const uint32_t*)(Pt + r0 + 16); \
                    a1[mt] = *(const uint32_t*)(Pt + r0 + 8 * PV_RS); \
                    a3[mt] = *(const uint32_t*)(Pt + r0 + 8 * PV_RS + 16); \
                } \
                _Pragma("unroll") \
                for (int nt2 = 0; nt2 < 8; ++nt2) { \
                    uint32_t rb = (uint32_t)(rn + nt2 * 8 + g) * PV_RS + so; \
                    uint32_t b0 = *(const uint32_t*)(Vt + rb); \
                    uint32_t b1 = *(const uint32_t*)(Vt + rb + 16); \
                    _Pragma("unroll") \
                    for (int mt = 0; mt < 4; ++mt) \
                        mma_f16(acc[mt][nt2], a0[mt], a1[mt], a2[mt], a3[mt], b0, b1); \
                } \
            } } while (0)

        PV_LOAD(0, 0); CP_COMMIT();
        if (NC > 1) { PV_LOAD(1, 1); }
        CP_COMMIT();
        for (int c = 0; c < NC; ++c) {
            CP_WAIT(1);
            __syncthreads();
            PV_COMPUTE(c % 3);
            if (c + 2 < NC) { PV_LOAD(c + 2, (c + 2) % 3); }
            CP_COMMIT();
        }

        const int* idxb = g_idx + b * L;
        #pragma unroll
        for (int mt = 0; mt < 4; ++mt) {
            int r0 = rm + mt * 16 + g;
            int i0 = ti + r0, i1 = i0 + 8;
            #pragma unroll
            for (int half = 0; half < 2; ++half) {
                int irow = half ? i1 : i0;
                if (irow < nv) {
                    float* orow = out + ((size_t)b * L + idxb[irow]) * D + td;
                    #pragma unroll
                    for (int nt2 = 0; nt2 < 8; ++nt2) {
                        int c0 = rn + nt2 * 8 + 2 * t;
                        *(float2*)(orow + c0) = half
                            ? make_float2(acc[mt][nt2][2], acc[mt][nt2][3])
                            : make_float2(acc[mt][nt2][0], acc[mt][nt2][1]);
                    }
                }
            }
        }
        __syncthreads();
    }
}

// ---------------------------------------------------------------------------
extern "C" void kernel_launch(void* const* d_in, const int* in_sizes, int n_in,
                              void* d_out, int out_size)
{
    const float* q    = (const float*)d_in[0];
    const float* k    = (const float*)d_in[1];
    const float* v    = (const float*)d_in[2];
    const int*   mask = (const int*)d_in[3];
    float*       out  = (float*)d_out;

    cudaFuncSetAttribute(qk_kernel, cudaFuncAttributeMaxDynamicSharedMemorySize, 2 * QK_STAGE);
    cudaFuncSetAttribute(pv_kernel, cudaFuncAttributeMaxDynamicSharedMemorySize, 3 * PV_STAGE);

    compact_kernel<<<B, 256>>>(mask);
    prep_qk_kernel<<<dim3((B * L * D / 16) / 256, 2, 1), 256>>>(q, k);
    prep_v_kernel<<<dim3(L / 64, D / 32, B), 256>>>(v);

    qk_kernel<<<GEMM_GRID, 128, 2 * QK_STAGE>>>();   // slot #4 -> ncu sample

    rowstats_kernel<<<B * L, 256>>>();

    pv_kernel<<<GEMM_GRID, 128, 3 * PV_STAGE>>>(out);

    zerofill_kernel<<<B * L, 256>>>(mask, out);
}